// round 2
// baseline (speedup 1.0000x reference)
#include <cuda_runtime.h>

#define NN   100000
#define NE   3200000
#define FEATD 256
#define HIDD  128
#define OUTD  64
#define HOPS  3

// ---------------- scratch (static __device__, no allocation) ----------------
__device__ float g_bufA[NN * HIDD];     // curr_s ping
__device__ float g_bufB[NN * HIDD];     // curr_t ping
__device__ float g_bufC[NN * HIDD];     // curr_s pong
__device__ float g_bufD[NN * HIDD];     // curr_t pong
__device__ float g_feat[NN * 2 * HIDD]; // [N,256] = [feat_s | feat_t]

__device__ int    g_cnt_s[NN];
__device__ int    g_cnt_t[NN];
__device__ int    g_ip_s[NN + 1];
__device__ int    g_ip_t[NN + 1];
__device__ int    g_pos_s[NN];
__device__ int    g_pos_t[NN];
__device__ float2 g_edge_s[NE];   // {.x = __int_as_float(col), .y = weight}
__device__ float2 g_edge_t[NE];

// ---------------- CSR build ----------------
__global__ void k_zero_counts() {
    int i = blockIdx.x * blockDim.x + threadIdx.x;
    if (i < NN) { g_cnt_s[i] = 0; g_cnt_t[i] = 0; }
}

__global__ void k_hist(const int* __restrict__ erow, const int* __restrict__ ecol, int E) {
    int e = blockIdx.x * blockDim.x + threadIdx.x;
    if (e >= E) return;
    atomicAdd(&g_cnt_s[erow[e]], 1);
    atomicAdd(&g_cnt_t[ecol[e]], 1);
}

// Exclusive scan of one counts array per block (blockIdx.x = 0: s, 1: t).
__global__ void k_scan() {
    __shared__ int sh[1024];
    __shared__ int carrySh;
    const int n = NN;
    const int* cnt = (blockIdx.x == 0) ? g_cnt_s : g_cnt_t;
    int* ip  = (blockIdx.x == 0) ? g_ip_s  : g_ip_t;
    int* pos = (blockIdx.x == 0) ? g_pos_s : g_pos_t;
    int tid = threadIdx.x;
    if (tid == 0) carrySh = 0;
    __syncthreads();
    for (int base = 0; base < n; base += 1024) {
        int i = base + tid;
        int v = (i < n) ? cnt[i] : 0;
        sh[tid] = v;
        __syncthreads();
        #pragma unroll
        for (int off = 1; off < 1024; off <<= 1) {
            int t = (tid >= off) ? sh[tid - off] : 0;
            __syncthreads();
            sh[tid] += t;
            __syncthreads();
        }
        int incl = sh[tid];
        int carry = carrySh;
        int excl = carry + incl - v;
        if (i < n) { ip[i] = excl; pos[i] = excl; }
        __syncthreads();
        if (tid == 1023) carrySh = carry + sh[1023];
        __syncthreads();
    }
    if (tid == 0) ip[n] = carrySh;
}

__global__ void k_scatter(const int* __restrict__ erow, const int* __restrict__ ecol,
                          const float* __restrict__ ew, int E) {
    int e = blockIdx.x * blockDim.x + threadIdx.x;
    if (e >= E) return;
    int r = erow[e], c = ecol[e];
    float wv = ew[e];
    int p = atomicAdd(&g_pos_s[r], 1);
    g_edge_s[p] = make_float2(__int_as_float(c), wv);
    int q = atomicAdd(&g_pos_t[c], 1);
    g_edge_t[q] = make_float2(__int_as_float(r), wv);
}

// ---------------- SpMM: one warp per node, float4 per lane ----------------
// gridDim.y = 2: y=0 -> source direction (adj), y=1 -> target direction (adj^T)
__global__ __launch_bounds__(256)
void k_spmm(int ping, int hop, const float* __restrict__ ws, const float* __restrict__ wt) {
    int gw = (blockIdx.x * 256 + threadIdx.x) >> 5;
    int lane = threadIdx.x & 31;
    if (gw >= NN) return;
    int dir = blockIdx.y;

    const int*    __restrict__ ip;
    const float2* __restrict__ eg;
    const float4* __restrict__ x;
    float4* nx;
    const float* wptr;
    int fOff;
    if (dir == 0) {
        ip = g_ip_s; eg = g_edge_s;
        x  = (const float4*)(ping ? g_bufC : g_bufA);
        nx = (float4*)(ping ? g_bufA : g_bufC);
        wptr = ws; fOff = 0;
    } else {
        ip = g_ip_t; eg = g_edge_t;
        x  = (const float4*)(ping ? g_bufD : g_bufB);
        nx = (float4*)(ping ? g_bufB : g_bufD);
        wptr = wt; fOff = 32;
    }

    int beg = ip[gw], end = ip[gw + 1];
    float4 acc = make_float4(0.f, 0.f, 0.f, 0.f);
    int e = beg;
    // 4-way unroll for MLP
    for (; e + 4 <= end; e += 4) {
        float2 e0 = __ldg(eg + e + 0);
        float2 e1 = __ldg(eg + e + 1);
        float2 e2 = __ldg(eg + e + 2);
        float2 e3 = __ldg(eg + e + 3);
        int c0 = __float_as_int(e0.x), c1 = __float_as_int(e1.x);
        int c2 = __float_as_int(e2.x), c3 = __float_as_int(e3.x);
        float4 v0 = __ldg(x + c0 * 32 + lane);
        float4 v1 = __ldg(x + c1 * 32 + lane);
        float4 v2 = __ldg(x + c2 * 32 + lane);
        float4 v3 = __ldg(x + c3 * 32 + lane);
        acc.x += e0.y * v0.x; acc.y += e0.y * v0.y; acc.z += e0.y * v0.z; acc.w += e0.y * v0.w;
        acc.x += e1.y * v1.x; acc.y += e1.y * v1.y; acc.z += e1.y * v1.z; acc.w += e1.y * v1.w;
        acc.x += e2.y * v2.x; acc.y += e2.y * v2.y; acc.z += e2.y * v2.z; acc.w += e2.y * v2.w;
        acc.x += e3.y * v3.x; acc.y += e3.y * v3.y; acc.z += e3.y * v3.z; acc.w += e3.y * v3.w;
    }
    for (; e < end; e++) {
        float2 ev = __ldg(eg + e);
        int c = __float_as_int(ev.x);
        float4 v = __ldg(x + c * 32 + lane);
        acc.x += ev.y * v.x; acc.y += ev.y * v.y; acc.z += ev.y * v.z; acc.w += ev.y * v.w;
    }

    nx[gw * 32 + lane] = acc;

    float wh = __ldg(wptr + hop);
    float4* frow = ((float4*)g_feat) + (size_t)gw * 64 + fOff;
    float4 f = frow[lane];
    f.x += wh * acc.x; f.y += wh * acc.y; f.z += wh * acc.z; f.w += wh * acc.w;
    frow[lane] = f;
}

// ---------------- SGEMM (fp32, shared-tiled, fused epilogue) ----------------
// MODE 0: out = feature_source@W_src+b  -> g_bufA ; g_feat[:,0:128)   = w0*out
// MODE 1: out = feature_target@W_tgt+b  -> g_bufB ; g_feat[:,128:256) = w0*out
// MODE 2: out = g_feat@W_node+b         -> extOut
template <int BN, int TN, int MODE>
__global__ __launch_bounds__(256)
void sgemm_k(const float* __restrict__ Ain, const float* __restrict__ W,
             const float* __restrict__ bias, const float* __restrict__ wptr,
             float* extOut, int M) {
    constexpr int BM = 128, BK = 8, TM = 8, K = FEATD;
    __shared__ float As[BK][BM];
    __shared__ float Ws[BK][BN];

    const float* A = (MODE == 2) ? (const float*)g_feat : Ain;
    float* out0;
    int ldo;
    if (MODE == 0)      { out0 = g_bufA; ldo = HIDD; }
    else if (MODE == 1) { out0 = g_bufB; ldo = HIDD; }
    else                { out0 = extOut; ldo = OUTD; }

    int tid = threadIdx.x;
    int rowBase = blockIdx.x * BM;

    int aRow = tid >> 1;
    int aCol = (tid & 1) * 4;
    constexpr int vecPerRow = BN / 4;
    constexpr int wThreads = BK * vecPerRow;
    int wRow = tid / vecPerRow;
    int wCol = (tid % vecPerRow) * 4;

    int tRow = tid >> 4;   // 0..15
    int tCol = tid & 15;   // 0..15

    float acc[TM][TN];
    #pragma unroll
    for (int i = 0; i < TM; i++)
        #pragma unroll
        for (int j = 0; j < TN; j++) acc[i][j] = 0.f;

    for (int k0 = 0; k0 < K; k0 += BK) {
        float4 a = make_float4(0.f, 0.f, 0.f, 0.f);
        int gRow = rowBase + aRow;
        if (gRow < M) a = *(const float4*)&A[(size_t)gRow * K + k0 + aCol];
        As[aCol + 0][aRow] = a.x;
        As[aCol + 1][aRow] = a.y;
        As[aCol + 2][aRow] = a.z;
        As[aCol + 3][aRow] = a.w;
        if (tid < wThreads) {
            float4 wv = *(const float4*)&W[(k0 + wRow) * BN + wCol];
            *(float4*)&Ws[wRow][wCol] = wv;
        }
        __syncthreads();
        #pragma unroll
        for (int kk = 0; kk < BK; kk++) {
            float rA[TM], rB[TN];
            #pragma unroll
            for (int i = 0; i < TM; i += 4)
                *(float4*)&rA[i] = *(const float4*)&As[kk][tRow * TM + i];
            #pragma unroll
            for (int j = 0; j < TN; j += 4)
                *(float4*)&rB[j] = *(const float4*)&Ws[kk][tCol * TN + j];
            #pragma unroll
            for (int i = 0; i < TM; i++)
                #pragma unroll
                for (int j = 0; j < TN; j++)
                    acc[i][j] += rA[i] * rB[j];
        }
        __syncthreads();
    }

    float bl[TN];
    #pragma unroll
    for (int j = 0; j < TN; j++) bl[j] = bias[tCol * TN + j];
    float w0 = 0.f;
    if (MODE < 2) w0 = __ldg(wptr);   // wptr[0]

    #pragma unroll
    for (int i = 0; i < TM; i++) {
        int gRow = rowBase + tRow * TM + i;
        if (gRow < M) {
            #pragma unroll
            for (int j4 = 0; j4 < TN; j4 += 4) {
                float4 v;
                v.x = acc[i][j4 + 0] + bl[j4 + 0];
                v.y = acc[i][j4 + 1] + bl[j4 + 1];
                v.z = acc[i][j4 + 2] + bl[j4 + 2];
                v.w = acc[i][j4 + 3] + bl[j4 + 3];
                *(float4*)&out0[(size_t)gRow * ldo + tCol * TN + j4] = v;
                if (MODE < 2) {
                    float4 fv;
                    fv.x = w0 * v.x; fv.y = w0 * v.y; fv.z = w0 * v.z; fv.w = w0 * v.w;
                    int fOff = (MODE == 0) ? 0 : HIDD;
                    *(float4*)&g_feat[(size_t)gRow * (2 * HIDD) + fOff + tCol * TN + j4] = fv;
                }
            }
        }
    }
}

// ---------------- launch ----------------
extern "C" void kernel_launch(void* const* d_in, const int* in_sizes, int n_in,
                              void* d_out, int out_size) {
    const float* fs    = (const float*)d_in[0];
    const float* ft    = (const float*)d_in[1];
    const int*   erow  = (const int*)d_in[2];
    const int*   ecol  = (const int*)d_in[3];
    const float* ew    = (const float*)d_in[4];
    const float* Wsrc  = (const float*)d_in[5];
    const float* bsrc  = (const float*)d_in[6];
    const float* Wtgt  = (const float*)d_in[7];
    const float* btgt  = (const float*)d_in[8];
    const float* ws    = (const float*)d_in[9];
    const float* wt    = (const float*)d_in[10];
    const float* Wnode = (const float*)d_in[11];
    const float* bnode = (const float*)d_in[12];
    float* out = (float*)d_out;

    const int M = NN;
    const int E = NE;

    // CSR build (adj by row, adj^T by col)
    k_zero_counts<<<(NN + 255) / 256, 256>>>();
    k_hist<<<(E + 255) / 256, 256>>>(erow, ecol, E);
    k_scan<<<2, 1024>>>();
    k_scatter<<<(E + 255) / 256, 256>>>(erow, ecol, ew, E);

    // input projections + feat init (hop 0)
    dim3 gg((M + 127) / 128);
    sgemm_k<128, 8, 0><<<gg, 256>>>(fs, Wsrc, bsrc, ws, nullptr, M);
    sgemm_k<128, 8, 1><<<gg, 256>>>(ft, Wtgt, btgt, wt, nullptr, M);

    // 3 hops, both directions fused in one launch (gridDim.y = 2)
    dim3 sg((NN * 32 + 255) / 256, 2);
    for (int h = 1; h <= HOPS; h++) {
        int ping = (h - 1) & 1;   // h=1: x=bufA/B, h=2: x=bufC/D, h=3: x=bufA/B
        k_spmm<<<sg, 256>>>(ping, h, ws, wt);
    }

    // final projection
    sgemm_k<64, 4, 2><<<gg, 256>>>(nullptr, Wnode, bnode, nullptr, out, M);
}

// round 4
// speedup vs baseline: 1.1736x; 1.1736x over previous
#include <cuda_runtime.h>
#include <cuda_fp16.h>

#define NN    100000
#define NE    3200000
#define FEATD 256
#define HIDD  128
#define OUTD  64
#define HOPS  3

#define XSZ ((size_t)NN * HIDD)

// ---------------- scratch (static __device__, no allocation) ----------------
// 8 half feature buffers: [dir*4 + hop] * XSZ,  dir 0 = source, 1 = target
__device__ __half g_xh[8 * (size_t)NN * HIDD];   // 204.8 MB

__device__ int    g_cnt_s[NN];
__device__ int    g_cnt_t[NN];
__device__ int    g_ip_s[NN + 1];
__device__ int    g_ip_t[NN + 1];
__device__ int    g_pos_s[NN];
__device__ int    g_pos_t[NN];
__device__ float2 g_edge_s[NE];   // {.x = __int_as_float(col), .y = weight}
__device__ float2 g_edge_t[NE];

// ---------------- CSR build ----------------
__global__ void k_zero_counts() {
    int i = blockIdx.x * blockDim.x + threadIdx.x;
    if (i < NN) { g_cnt_s[i] = 0; g_cnt_t[i] = 0; }
}

__global__ void k_hist(const int* __restrict__ erow, const int* __restrict__ ecol, int E) {
    int e = blockIdx.x * blockDim.x + threadIdx.x;
    if (e >= E) return;
    atomicAdd(&g_cnt_s[erow[e]], 1);
    atomicAdd(&g_cnt_t[ecol[e]], 1);
}

// Exclusive scan of one counts array per block (blockIdx.x = 0: s, 1: t).
__global__ void k_scan() {
    __shared__ int sh[1024];
    __shared__ int carrySh;
    const int n = NN;
    const int* cnt = (blockIdx.x == 0) ? g_cnt_s : g_cnt_t;
    int* ip  = (blockIdx.x == 0) ? g_ip_s  : g_ip_t;
    int* pos = (blockIdx.x == 0) ? g_pos_s : g_pos_t;
    int tid = threadIdx.x;
    if (tid == 0) carrySh = 0;
    __syncthreads();
    for (int base = 0; base < n; base += 1024) {
        int i = base + tid;
        int v = (i < n) ? cnt[i] : 0;
        sh[tid] = v;
        __syncthreads();
        #pragma unroll
        for (int off = 1; off < 1024; off <<= 1) {
            int t = (tid >= off) ? sh[tid - off] : 0;
            __syncthreads();
            sh[tid] += t;
            __syncthreads();
        }
        int incl = sh[tid];
        int carry = carrySh;
        int excl = carry + incl - v;
        if (i < n) { ip[i] = excl; pos[i] = excl; }
        __syncthreads();
        if (tid == 1023) carrySh = carry + sh[1023];
        __syncthreads();
    }
    if (tid == 0) ip[n] = carrySh;
}

__global__ void k_scatter(const int* __restrict__ erow, const int* __restrict__ ecol,
                          const float* __restrict__ ew, int E) {
    int e = blockIdx.x * blockDim.x + threadIdx.x;
    if (e >= E) return;
    int r = erow[e], c = ecol[e];
    float wv = ew[e];
    int p = atomicAdd(&g_pos_s[r], 1);
    g_edge_s[p] = make_float2(__int_as_float(c), wv);
    int q = atomicAdd(&g_pos_t[c], 1);
    g_edge_t[q] = make_float2(__int_as_float(r), wv);
}

// ---------------- SpMM: one warp per node, 4 halfs (8B) per lane ----------------
// gridDim.y = 2: y=0 -> source direction (adj), y=1 -> target direction (adj^T)
// x = g_xh[dir*4 + hop-1], next = g_xh[dir*4 + hop]; fp32 accumulation.
__global__ __launch_bounds__(256)
void k_spmm(int hop) {
    int gw = (blockIdx.x * 256 + threadIdx.x) >> 5;
    int lane = threadIdx.x & 31;
    if (gw >= NN) return;
    int dir = blockIdx.y;

    const int*    __restrict__ ip = dir ? g_ip_t   : g_ip_s;
    const float2* __restrict__ eg = dir ? g_edge_t : g_edge_s;
    const uint2*  __restrict__ x  = (const uint2*)(g_xh + ((size_t)(dir * 4 + hop - 1)) * XSZ);
    uint2* nx = (uint2*)(g_xh + ((size_t)(dir * 4 + hop)) * XSZ);

    int beg = ip[gw], end = ip[gw + 1];
    float4 acc = make_float4(0.f, 0.f, 0.f, 0.f);
    int e = beg;
    for (; e + 4 <= end; e += 4) {
        float2 e0 = __ldg(eg + e + 0);
        float2 e1 = __ldg(eg + e + 1);
        float2 e2 = __ldg(eg + e + 2);
        float2 e3 = __ldg(eg + e + 3);
        uint2 u0 = __ldg(x + (size_t)__float_as_int(e0.x) * 32 + lane);
        uint2 u1 = __ldg(x + (size_t)__float_as_int(e1.x) * 32 + lane);
        uint2 u2 = __ldg(x + (size_t)__float_as_int(e2.x) * 32 + lane);
        uint2 u3 = __ldg(x + (size_t)__float_as_int(e3.x) * 32 + lane);
        float2 a0 = __half22float2(*(__half2*)&u0.x), b0 = __half22float2(*(__half2*)&u0.y);
        float2 a1 = __half22float2(*(__half2*)&u1.x), b1 = __half22float2(*(__half2*)&u1.y);
        float2 a2 = __half22float2(*(__half2*)&u2.x), b2 = __half22float2(*(__half2*)&u2.y);
        float2 a3 = __half22float2(*(__half2*)&u3.x), b3 = __half22float2(*(__half2*)&u3.y);
        acc.x += e0.y * a0.x; acc.y += e0.y * a0.y; acc.z += e0.y * b0.x; acc.w += e0.y * b0.y;
        acc.x += e1.y * a1.x; acc.y += e1.y * a1.y; acc.z += e1.y * b1.x; acc.w += e1.y * b1.y;
        acc.x += e2.y * a2.x; acc.y += e2.y * a2.y; acc.z += e2.y * b2.x; acc.w += e2.y * b2.y;
        acc.x += e3.y * a3.x; acc.y += e3.y * a3.y; acc.z += e3.y * b3.x; acc.w += e3.y * b3.y;
    }
    for (; e < end; e++) {
        float2 ev = __ldg(eg + e);
        uint2 u = __ldg(x + (size_t)__float_as_int(ev.x) * 32 + lane);
        float2 a = __half22float2(*(__half2*)&u.x), b = __half22float2(*(__half2*)&u.y);
        acc.x += ev.y * a.x; acc.y += ev.y * a.y; acc.z += ev.y * b.x; acc.w += ev.y * b.y;
    }

    uint2 o;
    __half2 h0 = __floats2half2_rn(acc.x, acc.y);
    __half2 h1 = __floats2half2_rn(acc.z, acc.w);
    o.x = *(unsigned*)&h0; o.y = *(unsigned*)&h1;
    nx[(size_t)gw * 32 + lane] = o;
}

// ---------------- SGEMM (fp32 compute, shared-tiled) ----------------
// MODE 0 (gridDim.y = 2): y=0: g_xh[0] = fs@W_src+b ; y=1: g_xh[4] = ft@W_tgt+b
// MODE 2: out = [sum_h ws[h]*xs_h | sum_h wt[h]*xt_h] @ W_node + b
template <int BN, int TN, int MODE>
__global__ __launch_bounds__(256)
void sgemm_k(const float* __restrict__ A0, const float* __restrict__ A1,
             const float* __restrict__ W0, const float* __restrict__ W1,
             const float* __restrict__ b0, const float* __restrict__ b1,
             const float* __restrict__ ws, const float* __restrict__ wt,
             float* extOut, int M) {
    constexpr int BM = 128, BK = 8, TM = 8;
    constexpr int K = FEATD;   // MODE 0: input feat dim = 256; MODE 2: 2*HID = 256
    __shared__ float As[BK][BM];
    __shared__ float Wsm[BK][BN];

    int tid = threadIdx.x;
    int rowBase = blockIdx.x * BM;
    int ysel = blockIdx.y;   // MODE 0: 0 = source proj, 1 = target proj

    const float* Ain  = ysel ? A1 : A0;
    const float* W    = ysel ? W1 : W0;
    const float* bias = ysel ? b1 : b0;

    int aRow = tid >> 1;
    int aCol = (tid & 1) * 4;
    constexpr int vecPerRow = BN / 4;
    constexpr int wThreads = BK * vecPerRow;
    int wRow = tid / vecPerRow;
    int wCol = (tid % vecPerRow) * 4;

    int tRow = tid >> 4;   // 0..15
    int tCol = tid & 15;   // 0..15

    float acc[TM][TN];
    #pragma unroll
    for (int i = 0; i < TM; i++)
        #pragma unroll
        for (int j = 0; j < TN; j++) acc[i][j] = 0.f;

    for (int k0 = 0; k0 < K; k0 += BK) {
        int gRow = rowBase + aRow;
        if (MODE == 0) {
            float4 a = make_float4(0.f, 0.f, 0.f, 0.f);
            if (gRow < M) a = *(const float4*)&Ain[(size_t)gRow * K + k0 + aCol];
            As[aCol + 0][aRow] = a.x;
            As[aCol + 1][aRow] = a.y;
            As[aCol + 2][aRow] = a.z;
            As[aCol + 3][aRow] = a.w;
        } else {
            float a4[4] = {0.f, 0.f, 0.f, 0.f};
            if (gRow < M) {
                int kc = k0 + aCol;
                int dir = (kc >= HIDD) ? 1 : 0;
                int kk = kc - dir * HIDD;
                const float* wv = dir ? wt : ws;
                const __half* base = g_xh + ((size_t)dir * 4) * XSZ + (size_t)gRow * HIDD + kk;
                #pragma unroll
                for (int h = 0; h <= HOPS; h++) {
                    uint2 u = *(const uint2*)(base + (size_t)h * XSZ);
                    float2 f0 = __half22float2(*(__half2*)&u.x);
                    float2 f1 = __half22float2(*(__half2*)&u.y);
                    float w = __ldg(wv + h);
                    a4[0] += w * f0.x; a4[1] += w * f0.y;
                    a4[2] += w * f1.x; a4[3] += w * f1.y;
                }
            }
            As[aCol + 0][aRow] = a4[0];
            As[aCol + 1][aRow] = a4[1];
            As[aCol + 2][aRow] = a4[2];
            As[aCol + 3][aRow] = a4[3];
        }
        if (tid < wThreads) {
            float4 wv4 = *(const float4*)&W[(k0 + wRow) * BN + wCol];
            *(float4*)&Wsm[wRow][wCol] = wv4;
        }
        __syncthreads();
        #pragma unroll
        for (int kk = 0; kk < BK; kk++) {
            float rA[TM], rB[TN];
            #pragma unroll
            for (int i = 0; i < TM; i += 4)
                *(float4*)&rA[i] = *(const float4*)&As[kk][tRow * TM + i];
            #pragma unroll
            for (int j = 0; j < TN; j += 4)
                *(float4*)&rB[j] = *(const float4*)&Wsm[kk][tCol * TN + j];
            #pragma unroll
            for (int i = 0; i < TM; i++)
                #pragma unroll
                for (int j = 0; j < TN; j++)
                    acc[i][j] += rA[i] * rB[j];
        }
        __syncthreads();
    }

    float bl[TN];
    #pragma unroll
    for (int j = 0; j < TN; j++) bl[j] = bias[tCol * TN + j];

    #pragma unroll
    for (int i = 0; i < TM; i++) {
        int gRow = rowBase + tRow * TM + i;
        if (gRow < M) {
            if (MODE == 2) {
                #pragma unroll
                for (int j4 = 0; j4 < TN; j4 += 4) {
                    float4 v;
                    v.x = acc[i][j4 + 0] + bl[j4 + 0];
                    v.y = acc[i][j4 + 1] + bl[j4 + 1];
                    v.z = acc[i][j4 + 2] + bl[j4 + 2];
                    v.w = acc[i][j4 + 3] + bl[j4 + 3];
                    *(float4*)&extOut[(size_t)gRow * OUTD + tCol * TN + j4] = v;
                }
            } else {
                // write hop-0 half state: g_xh[ysel*4 + 0]
                __half* outh = g_xh + ((size_t)(ysel * 4)) * XSZ + (size_t)gRow * HIDD + tCol * TN;
                uint4 pk;
                __half2 p0 = __floats2half2_rn(acc[i][0] + bl[0], acc[i][1] + bl[1]);
                __half2 p1 = __floats2half2_rn(acc[i][2] + bl[2], acc[i][3] + bl[3]);
                __half2 p2 = __floats2half2_rn(acc[i][4] + bl[4], acc[i][5] + bl[5]);
                __half2 p3 = __floats2half2_rn(acc[i][6] + bl[6], acc[i][7] + bl[7]);
                pk.x = *(unsigned*)&p0; pk.y = *(unsigned*)&p1;
                pk.z = *(unsigned*)&p2; pk.w = *(unsigned*)&p3;
                *(uint4*)outh = pk;
            }
        }
    }
}

// ---------------- launch ----------------
extern "C" void kernel_launch(void* const* d_in, const int* in_sizes, int n_in,
                              void* d_out, int out_size) {
    const float* fs    = (const float*)d_in[0];
    const float* ft    = (const float*)d_in[1];
    const int*   erow  = (const int*)d_in[2];
    const int*   ecol  = (const int*)d_in[3];
    const float* ew    = (const float*)d_in[4];
    const float* Wsrc  = (const float*)d_in[5];
    const float* bsrc  = (const float*)d_in[6];
    const float* Wtgt  = (const float*)d_in[7];
    const float* btgt  = (const float*)d_in[8];
    const float* ws    = (const float*)d_in[9];
    const float* wt    = (const float*)d_in[10];
    const float* Wnode = (const float*)d_in[11];
    const float* bnode = (const float*)d_in[12];
    float* out = (float*)d_out;

    const int M = NN;
    const int E = NE;

    // CSR build (adj by row, adj^T by col)
    k_zero_counts<<<(NN + 255) / 256, 256>>>();
    k_hist<<<(E + 255) / 256, 256>>>(erow, ecol, E);
    k_scan<<<2, 1024>>>();
    k_scatter<<<(E + 255) / 256, 256>>>(erow, ecol, ew, E);

    // both input projections in one launch -> hop-0 half states
    dim3 gg((M + 127) / 128, 2);
    sgemm_k<128, 8, 0><<<gg, 256>>>(fs, ft, Wsrc, Wtgt, bsrc, btgt,
                                    nullptr, nullptr, nullptr, M);

    // 3 hops, both directions fused in one launch (gridDim.y = 2)
    dim3 sg((NN * 32 + 255) / 256, 2);
    for (int h = 1; h <= HOPS; h++) {
        k_spmm<<<sg, 256>>>(h);
    }

    // final projection with fused hop-weighted feature combine
    dim3 gf((M + 127) / 128);
    sgemm_k<64, 4, 2><<<gf, 256>>>(nullptr, nullptr, Wnode, nullptr, bnode, nullptr,
                                   ws, wt, out, M);
}

// round 6
// speedup vs baseline: 1.7016x; 1.4499x over previous
#include <cuda_runtime.h>
#include <cuda_fp16.h>

#define NN    100000
#define NE    3200000
#define FEATD 256
#define HIDD  128
#define OUTD  64
#define HOPS  3

#define XSZ ((size_t)NN * HIDD)
#define SCAN_BLKS 98   // ceil(NN / 1024)

// ---------------- scratch (static __device__, no allocation) ----------------
// 8 half feature buffers: [dir*4 + hop] * XSZ,  dir 0 = source, 1 = target
__device__ __half g_xh[8 * (size_t)NN * HIDD];   // 204.8 MB

__device__ int    g_cnt_s[NN];
__device__ int    g_cnt_t[NN];
__device__ int    g_ip_s[NN + 1];
__device__ int    g_ip_t[NN + 1];
__device__ int    g_pos_s[NN];
__device__ int    g_pos_t[NN];
__device__ float2 g_edge_s[NE];   // {.x = __int_as_float(col), .y = weight}
__device__ float2 g_edge_t[NE];
__device__ int    g_bsum[2 * SCAN_BLKS];
__device__ uint2  g_wf[2 * 16 * 16 * 32];   // fragment-packed W_src/W_tgt (fp16)

// ---------------- CSR build ----------------
__global__ void k_zero_counts() {
    int i = blockIdx.x * blockDim.x + threadIdx.x;
    if (i < NN) { g_cnt_s[i] = 0; g_cnt_t[i] = 0; }
}

__global__ void k_hist(const int* __restrict__ erow, const int* __restrict__ ecol, int E) {
    int e = blockIdx.x * blockDim.x + threadIdx.x;
    if (e >= E) return;
    atomicAdd(&g_cnt_s[erow[e]], 1);
    atomicAdd(&g_cnt_t[ecol[e]], 1);
}

// ---- 3-phase exclusive scan over g_cnt_{s,t} (gridDim.y selects array) ----
__global__ void k_scan1() {   // grid (SCAN_BLKS, 2), block 256: per-block sums
    const int* cnt = blockIdx.y ? g_cnt_t : g_cnt_s;
    __shared__ int sh[256];
    int t = threadIdx.x;
    int base = blockIdx.x * 1024 + t * 4;
    int4 v = make_int4(0, 0, 0, 0);
    if (base + 3 < NN) v = *(const int4*)(cnt + base);
    else if (base < NN) {
        v.x = cnt[base];
        if (base + 1 < NN) v.y = cnt[base + 1];
        if (base + 2 < NN) v.z = cnt[base + 2];
    }
    sh[t] = v.x + v.y + v.z + v.w;
    __syncthreads();
    for (int off = 128; off > 0; off >>= 1) {
        if (t < off) sh[t] += sh[t + off];
        __syncthreads();
    }
    if (t == 0) g_bsum[blockIdx.y * SCAN_BLKS + blockIdx.x] = sh[0];
}

__global__ void k_scan2() {   // grid 2, block 128: exclusive-scan the partials
    __shared__ int sh[128];
    int* bs = g_bsum + blockIdx.x * SCAN_BLKS;
    int t = threadIdx.x;
    int v = (t < SCAN_BLKS) ? bs[t] : 0;
    sh[t] = v;
    __syncthreads();
    for (int off = 1; off < 128; off <<= 1) {
        int a = (t >= off) ? sh[t - off] : 0;
        __syncthreads();
        sh[t] += a;
        __syncthreads();
    }
    if (t < SCAN_BLKS) bs[t] = sh[t] - v;
}

__global__ void k_scan3() {   // grid (SCAN_BLKS, 2), block 256: final scatter of offsets
    const int* cnt = blockIdx.y ? g_cnt_t : g_cnt_s;
    int* ip  = blockIdx.y ? g_ip_t  : g_ip_s;
    int* pos = blockIdx.y ? g_pos_t : g_pos_s;
    __shared__ int sh[256];
    int t = threadIdx.x;
    int base = blockIdx.x * 1024 + t * 4;
    int4 v = make_int4(0, 0, 0, 0);
    if (base + 3 < NN) v = *(const int4*)(cnt + base);
    else if (base < NN) {
        v.x = cnt[base];
        if (base + 1 < NN) v.y = cnt[base + 1];
        if (base + 2 < NN) v.z = cnt[base + 2];
    }
    int tsum = v.x + v.y + v.z + v.w;
    sh[t] = tsum;
    __syncthreads();
    for (int off = 1; off < 256; off <<= 1) {
        int a = (t >= off) ? sh[t - off] : 0;
        __syncthreads();
        sh[t] += a;
        __syncthreads();
    }
    int toff = g_bsum[blockIdx.y * SCAN_BLKS + blockIdx.x] + sh[t] - tsum;
    int e0 = toff, e1 = toff + v.x, e2 = e1 + v.y, e3 = e2 + v.z;
    if (base     < NN) { ip[base]     = e0; pos[base]     = e0; }
    if (base + 1 < NN) { ip[base + 1] = e1; pos[base + 1] = e1; }
    if (base + 2 < NN) { ip[base + 2] = e2; pos[base + 2] = e2; }
    if (base <= NN - 1 && NN - 1 < base + 4) {
        int ex[4] = {e0, e1, e2, e3};
        int cv[4] = {v.x, v.y, v.z, v.w};
        int idx = NN - 1 - base;
        ip[NN] = ex[idx] + cv[idx];
    }
    if (base + 3 < NN) { ip[base + 3] = e3; pos[base + 3] = e3; }
}

__global__ void k_scatter(const int* __restrict__ erow, const int* __restrict__ ecol,
                          const float* __restrict__ ew, int E) {
    int e = blockIdx.x * blockDim.x + threadIdx.x;
    if (e >= E) return;
    int r = erow[e], c = ecol[e];
    float wv = ew[e];
    int p = atomicAdd(&g_pos_s[r], 1);
    g_edge_s[p] = make_float2(__int_as_float(c), wv);
    int q = atomicAdd(&g_pos_t[c], 1);
    g_edge_t[q] = make_float2(__int_as_float(r), wv);
}

// ---------------- SpMM: one warp per node, 4 halfs (8B) per lane ----------------
__global__ __launch_bounds__(256)
void k_spmm(int hop) {
    int gw = (blockIdx.x * 256 + threadIdx.x) >> 5;
    int lane = threadIdx.x & 31;
    if (gw >= NN) return;
    int dir = blockIdx.y;

    const int*    __restrict__ ip = dir ? g_ip_t   : g_ip_s;
    const float2* __restrict__ eg = dir ? g_edge_t : g_edge_s;
    const uint2*  __restrict__ x  = (const uint2*)(g_xh + ((size_t)(dir * 4 + hop - 1)) * XSZ);
    uint2* nx = (uint2*)(g_xh + ((size_t)(dir * 4 + hop)) * XSZ);

    int beg = ip[gw], end = ip[gw + 1];
    float4 acc = make_float4(0.f, 0.f, 0.f, 0.f);
    int e = beg;
    for (; e + 4 <= end; e += 4) {
        float2 e0 = __ldg(eg + e + 0);
        float2 e1 = __ldg(eg + e + 1);
        float2 e2 = __ldg(eg + e + 2);
        float2 e3 = __ldg(eg + e + 3);
        uint2 u0 = __ldg(x + (size_t)__float_as_int(e0.x) * 32 + lane);
        uint2 u1 = __ldg(x + (size_t)__float_as_int(e1.x) * 32 + lane);
        uint2 u2 = __ldg(x + (size_t)__float_as_int(e2.x) * 32 + lane);
        uint2 u3 = __ldg(x + (size_t)__float_as_int(e3.x) * 32 + lane);
        float2 a0 = __half22float2(*(__half2*)&u0.x), b0 = __half22float2(*(__half2*)&u0.y);
        float2 a1 = __half22float2(*(__half2*)&u1.x), b1 = __half22float2(*(__half2*)&u1.y);
        float2 a2 = __half22float2(*(__half2*)&u2.x), b2 = __half22float2(*(__half2*)&u2.y);
        float2 a3 = __half22float2(*(__half2*)&u3.x), b3 = __half22float2(*(__half2*)&u3.y);
        acc.x += e0.y * a0.x; acc.y += e0.y * a0.y; acc.z += e0.y * b0.x; acc.w += e0.y * b0.y;
        acc.x += e1.y * a1.x; acc.y += e1.y * a1.y; acc.z += e1.y * b1.x; acc.w += e1.y * b1.y;
        acc.x += e2.y * a2.x; acc.y += e2.y * a2.y; acc.z += e2.y * b2.x; acc.w += e2.y * b2.y;
        acc.x += e3.y * a3.x; acc.y += e3.y * a3.y; acc.z += e3.y * b3.x; acc.w += e3.y * b3.y;
    }
    for (; e < end; e++) {
        float2 ev = __ldg(eg + e);
        uint2 u = __ldg(x + (size_t)__float_as_int(ev.x) * 32 + lane);
        float2 a = __half22float2(*(__half2*)&u.x), b = __half22float2(*(__half2*)&u.y);
        acc.x += ev.y * a.x; acc.y += ev.y * a.y; acc.z += ev.y * b.x; acc.w += ev.y * b.y;
    }

    uint2 o;
    __half2 h0 = __floats2half2_rn(acc.x, acc.y);
    __half2 h1 = __floats2half2_rn(acc.z, acc.w);
    o.x = *(unsigned*)&h0; o.y = *(unsigned*)&h1;
    nx[(size_t)gw * 32 + lane] = o;
}

// ---------------- tensor-core input projections ----------------
// Pack W_src/W_tgt into mma B-fragment order: [dir][kt][nt][lane] -> uint2{b0,b1}
__global__ void k_packw(const float* __restrict__ Wsrc, const float* __restrict__ Wtgt) {
    int i = blockIdx.x * 256 + threadIdx.x;
    if (i >= 2 * 16 * 16 * 32) return;
    int lane = i & 31;
    int nt   = (i >> 5) & 15;
    int kt   = (i >> 9) & 15;
    int dir  = i >> 13;
    const float* W = dir ? Wtgt : Wsrc;
    int gr = lane >> 2, ci = lane & 3;
    int n = nt * 8 + gr;
    int k = kt * 16 + 2 * ci;
    __half2 h0 = __floats2half2_rn(W[k * HIDD + n],       W[(k + 1) * HIDD + n]);
    __half2 h1 = __floats2half2_rn(W[(k + 8) * HIDD + n], W[(k + 9) * HIDD + n]);
    uint2 u; u.x = *(unsigned*)&h0; u.y = *(unsigned*)&h1;
    g_wf[i] = u;
}

__device__ __forceinline__ void mma16816(float* d, const unsigned* a, unsigned b0, unsigned b1) {
    asm("mma.sync.aligned.m16n8k16.row.col.f32.f16.f16.f32 "
        "{%0,%1,%2,%3},{%4,%5,%6,%7},{%8,%9},{%0,%1,%2,%3};"
        : "+f"(d[0]), "+f"(d[1]), "+f"(d[2]), "+f"(d[3])
        : "r"(a[0]), "r"(a[1]), "r"(a[2]), "r"(a[3]), "r"(b0), "r"(b1));
}

__device__ __forceinline__ unsigned packh2(float2 f) {
    __half2 h = __floats2half2_rn(f.x, f.y);
    return *(unsigned*)&h;
}

// grid (ceil(NN/128), 2), block 256 (8 warps: 4 M-warps x 2 N-warps).
// out g_xh[dir*4] = A(dir) @ W(dir) + b(dir), A fp32 read direct, no smem.
__global__ __launch_bounds__(256)
void k_gemm0_mma(const float* __restrict__ fs, const float* __restrict__ ft,
                 const float* __restrict__ bsrc, const float* __restrict__ btgt) {
    int dir = blockIdx.y;
    const float* A    = dir ? ft : fs;
    const float* bias = dir ? btgt : bsrc;
    const uint2* wf = g_wf + (size_t)dir * 16 * 16 * 32;
    __half* outp = g_xh + (size_t)dir * 4 * XSZ;

    int tid = threadIdx.x, lane = tid & 31, warp = tid >> 5;
    int wm = warp & 3, wn = warp >> 2;
    int gr = lane >> 2, ci = lane & 3;
    int rowBase = blockIdx.x * 128 + wm * 32;

    float d[2][8][4];
    #pragma unroll
    for (int mt = 0; mt < 2; mt++)
        #pragma unroll
        for (int j = 0; j < 8; j++)
            #pragma unroll
            for (int q = 0; q < 4; q++) d[mt][j][q] = 0.f;

    int rA[2][2];   // [mt][half]: rows gr, gr+8 (clamped for loads)
    rA[0][0] = min(rowBase + gr,          NN - 1);
    rA[0][1] = min(rowBase + gr + 8,      NN - 1);
    rA[1][0] = min(rowBase + 16 + gr,     NN - 1);
    rA[1][1] = min(rowBase + 16 + gr + 8, NN - 1);

    for (int kt = 0; kt < 16; kt++) {
        int k0 = kt * 16 + 2 * ci;
        unsigned afr[2][4];
        #pragma unroll
        for (int mt = 0; mt < 2; mt++) {
            afr[mt][0] = packh2(*(const float2*)(A + (size_t)rA[mt][0] * FEATD + k0));
            afr[mt][1] = packh2(*(const float2*)(A + (size_t)rA[mt][1] * FEATD + k0));
            afr[mt][2] = packh2(*(const float2*)(A + (size_t)rA[mt][0] * FEATD + k0 + 8));
            afr[mt][3] = packh2(*(const float2*)(A + (size_t)rA[mt][1] * FEATD + k0 + 8));
        }
        uint2 bfr[8];
        #pragma unroll
        for (int j = 0; j < 8; j++)
            bfr[j] = __ldg(wf + ((size_t)kt * 16 + wn * 8 + j) * 32 + lane);
        #pragma unroll
        for (int mt = 0; mt < 2; mt++)
            #pragma unroll
            for (int j = 0; j < 8; j++)
                mma16816(d[mt][j], afr[mt], bfr[j].x, bfr[j].y);
    }

    #pragma unroll
    for (int mt = 0; mt < 2; mt++) {
        int ra = rowBase + mt * 16 + gr;
        int rb = ra + 8;
        #pragma unroll
        for (int j = 0; j < 8; j++) {
            int c = wn * 64 + j * 8 + 2 * ci;
            float2 bb = *(const float2*)(bias + c);
            if (ra < NN) {
                __half2 h = __floats2half2_rn(d[mt][j][0] + bb.x, d[mt][j][1] + bb.y);
                *(__half2*)(outp + (size_t)ra * HIDD + c) = h;
            }
            if (rb < NN) {
                __half2 h = __floats2half2_rn(d[mt][j][2] + bb.x, d[mt][j][3] + bb.y);
                *(__half2*)(outp + (size_t)rb * HIDD + c) = h;
            }
        }
    }
}

// ---------------- final GEMM (SIMT fp32) with fused hop combine ----------------
// out = [sum_h ws[h]*xs_h | sum_h wt[h]*xt_h] @ W_node + b
__global__ __launch_bounds__(256)
void k_gemm2(const float* __restrict__ W, const float* __restrict__ bias,
             const float* __restrict__ ws, const float* __restrict__ wt,
             float* __restrict__ extOut, int M) {
    constexpr int BM = 128, BN = 64, BK = 8, TM = 8, TN = 4;
    constexpr int K = 2 * HIDD;
    __shared__ float As[BK][BM];
    __shared__ float Wsm[BK][BN];

    int tid = threadIdx.x;
    int rowBase = blockIdx.x * BM;

    int aRow = tid >> 1;
    int aCol = (tid & 1) * 4;
    constexpr int vecPerRow = BN / 4;
    constexpr int wThreads = BK * vecPerRow;
    int wRow = tid / vecPerRow;
    int wCol = (tid % vecPerRow) * 4;

    int tRow = tid >> 4;
    int tCol = tid & 15;

    float acc[TM][TN];
    #pragma unroll
    for (int i = 0; i < TM; i++)
        #pragma unroll
        for (int j = 0; j < TN; j++) acc[i][j] = 0.f;

    for (int k0 = 0; k0 < K; k0 += BK) {
        int gRow = rowBase + aRow;
        float a4[4] = {0.f, 0.f, 0.f, 0.f};
        if (gRow < M) {
            int kc = k0 + aCol;
            int dir = (kc >= HIDD) ? 1 : 0;
            int kk = kc - dir * HIDD;
            const float* wv = dir ? wt : ws;
            const __half* base = g_xh + ((size_t)dir * 4) * XSZ + (size_t)gRow * HIDD + kk;
            #pragma unroll
            for (int h = 0; h <= HOPS; h++) {
                uint2 u = *(const uint2*)(base + (size_t)h * XSZ);
                float2 f0 = __half22float2(*(__half2*)&u.x);
                float2 f1 = __half22float2(*(__half2*)&u.y);
                float w = __ldg(wv + h);
                a4[0] += w * f0.x; a4[1] += w * f0.y;
                a4[2] += w * f1.x; a4[3] += w * f1.y;
            }
        }
        As[aCol + 0][aRow] = a4[0];
        As[aCol + 1][aRow] = a4[1];
        As[aCol + 2][aRow] = a4[2];
        As[aCol + 3][aRow] = a4[3];
        if (tid < wThreads) {
            float4 wv4 = *(const float4*)&W[(k0 + wRow) * BN + wCol];
            *(float4*)&Wsm[wRow][wCol] = wv4;
        }
        __syncthreads();
        #pragma unroll
        for (int kk2 = 0; kk2 < BK; kk2++) {
            float rAr[TM], rB[TN];
            #pragma unroll
            for (int i = 0; i < TM; i += 4)
                *(float4*)&rAr[i] = *(const float4*)&As[kk2][tRow * TM + i];
            #pragma unroll
            for (int j = 0; j < TN; j += 4)
                *(float4*)&rB[j] = *(const float4*)&Wsm[kk2][tCol * TN + j];
            #pragma unroll
            for (int i = 0; i < TM; i++)
                #pragma unroll
                for (int j = 0; j < TN; j++)
                    acc[i][j] += rAr[i] * rB[j];
        }
        __syncthreads();
    }

    float bl[TN];
    #pragma unroll
    for (int j = 0; j < TN; j++) bl[j] = bias[tCol * TN + j];

    #pragma unroll
    for (int i = 0; i < TM; i++) {
        int gRow = rowBase + tRow * TM + i;
        if (gRow < M) {
            float4 v;
            v.x = acc[i][0] + bl[0];
            v.y = acc[i][1] + bl[1];
            v.z = acc[i][2] + bl[2];
            v.w = acc[i][3] + bl[3];
            *(float4*)&extOut[(size_t)gRow * OUTD + tCol * TN] = v;
        }
    }
}

// ---------------- launch ----------------
extern "C" void kernel_launch(void* const* d_in, const int* in_sizes, int n_in,
                              void* d_out, int out_size) {
    const float* fs    = (const float*)d_in[0];
    const float* ft    = (const float*)d_in[1];
    const int*   erow  = (const int*)d_in[2];
    const int*   ecol  = (const int*)d_in[3];
    const float* ew    = (const float*)d_in[4];
    const float* Wsrc  = (const float*)d_in[5];
    const float* bsrc  = (const float*)d_in[6];
    const float* Wtgt  = (const float*)d_in[7];
    const float* btgt  = (const float*)d_in[8];
    const float* ws    = (const float*)d_in[9];
    const float* wt    = (const float*)d_in[10];
    const float* Wnode = (const float*)d_in[11];
    const float* bnode = (const float*)d_in[12];
    float* out = (float*)d_out;

    const int M = NN;
    const int E = NE;

    // input projections (tensor core) -> hop-0 half states
    k_packw<<<64, 256>>>(Wsrc, Wtgt);
    k_gemm0_mma<<<dim3((M + 127) / 128, 2), 256>>>(fs, ft, bsrc, btgt);

    // CSR build (adj by row, adj^T by col)
    k_zero_counts<<<(NN + 255) / 256, 256>>>();
    k_hist<<<(E + 255) / 256, 256>>>(erow, ecol, E);
    k_scan1<<<dim3(SCAN_BLKS, 2), 256>>>();
    k_scan2<<<2, 128>>>();
    k_scan3<<<dim3(SCAN_BLKS, 2), 256>>>();
    k_scatter<<<(E + 255) / 256, 256>>>(erow, ecol, ew, E);

    // 3 hops, both directions fused in one launch (gridDim.y = 2)
    dim3 sg((NN * 32 + 255) / 256, 2);
    for (int h = 1; h <= HOPS; h++) {
        k_spmm<<<sg, 256>>>(h);
    }

    // final projection with fused hop-weighted feature combine
    k_gemm2<<<(M + 127) / 128, 256>>>(Wnode, bnode, ws, wt, out, M);
}